// round 15
// baseline (speedup 1.0000x reference)
#include <cuda_runtime.h>
#include <cuda_fp16.h>
#include <math.h>

// ---------------------------------------------------------------------------
// EPA_Layer: B=16, H=W=64, C=256, HID=64
// Round 14 (= Round 12 ldmatrix kernel, third submission after broker flakes):
//   k_attn via ldmatrix/.trans on a single natural smem image (kills the
//   16-way STS conflicts of the dual-image build). Rest = Round 11 pipeline
//   (channels-last fp16, BN=128 tiles, pool fused into softmax).
// ---------------------------------------------------------------------------

#define NB   16
#define NC   256
#define NHW  4096
#define NM   65536

__device__ __half g_qh [NB * NC * NHW];   // q fp16 [B,C,H,W]
__device__ __half g_kh [NB * NC * NHW];   // k fp16 [B,C,H,W]
__device__ __half g_vch[NM * NC];         // vc fp16 [B,H,W,C]
__device__ __half g_vsh[NM * NC];         // vs fp16 [B,H,W,C]
__device__ float  g_as [NB * NC * NHW];   // attn_s logits fp32 [B,C,64,64]
__device__ float  g_ac [NB * NC * NHW];   // attn_c logits fp32 [B,C,64,64]
__device__ __half g_ash[NB * NHW * NC];   // softmax(attn_s) fp16 [B,64,64,C]
__device__ __half g_ach[NB * NHW * NC];   // softmax(attn_c) fp16 [B,64,64,C]
__device__ __half g_c1h[NB * 1024 * NC];  // conv out fp16 [B,32,32,C]
__device__ __half g_sbh[NB * NHW * NC];   // convT out fp16 [B,64,64,C]
__device__ __half g_wch[NC * 2304];       // conv weights [co][tap*256+ci]
__device__ __half g_wt2[4 * NC * 1024];   // convT weights [cl][co][t*256+ci]
__device__ float  g_poolp[NB * 128 * NC]; // pool partials (per softmax block)
__device__ float  g_gate[NB * NC];

__device__ __forceinline__ unsigned packh2(float a, float b) {
    __half2 h = __floats2half2_rn(a, b);
    return *(unsigned*)&h;
}
__device__ __forceinline__ void mma_f16(float* c, const unsigned* a, const unsigned* b) {
    asm volatile(
        "mma.sync.aligned.m16n8k16.row.col.f32.f16.f16.f32 "
        "{%0,%1,%2,%3}, {%4,%5,%6,%7}, {%8,%9}, {%0,%1,%2,%3};"
        : "+f"(c[0]), "+f"(c[1]), "+f"(c[2]), "+f"(c[3])
        : "r"(a[0]), "r"(a[1]), "r"(a[2]), "r"(a[3]), "r"(b[0]), "r"(b[1]));
}
__device__ __forceinline__ void unp8(uint4 u, float* f) {
    const __half2* h = (const __half2*)&u;
    #pragma unroll
    for (int q = 0; q < 4; q++) {
        float2 t = __half22float2(h[q]);
        f[2 * q] = t.x; f[2 * q + 1] = t.y;
    }
}
__device__ __forceinline__ unsigned sptr(const void* p) {
    return (unsigned)__cvta_generic_to_shared(p);
}
__device__ __forceinline__ void ldsm_x4(unsigned& r0, unsigned& r1,
                                        unsigned& r2, unsigned& r3, unsigned addr) {
    asm volatile("ldmatrix.sync.aligned.m8n8.x4.shared.b16 {%0,%1,%2,%3}, [%4];"
        : "=r"(r0), "=r"(r1), "=r"(r2), "=r"(r3) : "r"(addr));
}
__device__ __forceinline__ void ldsm_x4t(unsigned& r0, unsigned& r1,
                                         unsigned& r2, unsigned& r3, unsigned addr) {
    asm volatile("ldmatrix.sync.aligned.m8n8.x4.trans.shared.b16 {%0,%1,%2,%3}, [%4];"
        : "=r"(r0), "=r"(r1), "=r"(r2), "=r"(r3) : "r"(addr));
}

// ---------------------------------------------------------------------------
// Weight repacks
// ---------------------------------------------------------------------------
__global__ void k_packc(const float* __restrict__ Wconv)
{
    int co = blockIdx.x, ci = threadIdx.x;
    #pragma unroll
    for (int tap = 0; tap < 9; tap++)
        g_wch[co * 2304 + tap * 256 + ci] =
            __float2half(Wconv[co * 2304 + ci * 9 + tap]);
}
__global__ void k_packt(const float* __restrict__ Wconvt)
{
    int cl = blockIdx.x >> 8, co = blockIdx.x & 255, ci = threadIdx.x;
    int py = cl >> 1, px = cl & 1;
    #pragma unroll
    for (int t = 0; t < 4; t++) {
        int tyk = t >> 1, txk = t & 1;
        int ky = 1 - py + 2 * tyk, kx = 1 - px + 2 * txk;
        g_wt2[(size_t)((cl << 8) + co) * 1024 + (t << 8) + ci] =
            __float2half(Wconvt[(size_t)ci * 4096 + co * 16 + (ky << 2) + kx]);
    }
}

// ---------------------------------------------------------------------------
// K1: unified 4-way projection (fp16 mma). BM=128, BN=128, BK=32.
// ---------------------------------------------------------------------------
__global__ __launch_bounds__(256) void k_proj(
    const float* __restrict__ x,
    const float* __restrict__ Wq, const float* __restrict__ Wk,
    const float* __restrict__ Wvc, const float* __restrict__ Wvs)
{
    __shared__ unsigned As[128][20];
    __shared__ unsigned Bs[128][20];
    int m0 = blockIdx.x << 7;
    int nb = blockIdx.y;
    int which = nb >> 1;
    int d0 = (nb & 1) << 7;
    const float* W = (which == 0) ? Wq : (which == 1) ? Wk : (which == 2) ? Wvc : Wvs;
    int tid = threadIdx.x, lane = tid & 31, wid = tid >> 5;
    int warpM = wid >> 1, warpN = wid & 1;
    int g = lane >> 2, tig = lane & 3;
    float acc[2][8][4] = {};
    float4 ra[4], rb[4];

    auto gload = [&](int k0) {
        #pragma unroll
        for (int l = 0; l < 4; l++) {
            int idx = tid + (l << 8);
            ra[l] = *(const float4*)&x[(size_t)(m0 + (idx >> 3)) * 256 + k0 + ((idx & 7) << 2)];
            rb[l] = *(const float4*)&W[(size_t)(d0 + (idx >> 3)) * 256 + k0 + ((idx & 7) << 2)];
        }
    };
    auto sstore = [&]() {
        #pragma unroll
        for (int l = 0; l < 4; l++) {
            int idx = tid + (l << 8);
            *(uint2*)&As[idx >> 3][(idx & 7) << 1] =
                make_uint2(packh2(ra[l].x, ra[l].y), packh2(ra[l].z, ra[l].w));
            *(uint2*)&Bs[idx >> 3][(idx & 7) << 1] =
                make_uint2(packh2(rb[l].x, rb[l].y), packh2(rb[l].z, rb[l].w));
        }
    };

    gload(0); sstore(); __syncthreads();
    for (int k0 = 0; k0 < 256; k0 += 32) {
        bool more = (k0 + 32) < 256;
        if (more) gload(k0 + 32);
        #pragma unroll
        for (int ks = 0; ks < 2; ks++) {
            int kb = ks << 3;
            unsigned a[2][4], bf[8][2];
            #pragma unroll
            for (int mt = 0; mt < 2; mt++) {
                int row = (warpM << 5) + (mt << 4) + g;
                a[mt][0] = As[row][kb + tig];     a[mt][1] = As[row + 8][kb + tig];
                a[mt][2] = As[row][kb + 4 + tig]; a[mt][3] = As[row + 8][kb + 4 + tig];
            }
            #pragma unroll
            for (int nt = 0; nt < 8; nt++) {
                int col = (warpN << 6) + (nt << 3) + g;
                bf[nt][0] = Bs[col][kb + tig]; bf[nt][1] = Bs[col][kb + 4 + tig];
            }
            #pragma unroll
            for (int mt = 0; mt < 2; mt++)
                #pragma unroll
                for (int nt = 0; nt < 8; nt++)
                    mma_f16(acc[mt][nt], a[mt], bf[nt]);
        }
        __syncthreads();
        if (more) { sstore(); __syncthreads(); }
    }

    if (which < 2) {
        __half* dst = which ? g_kh : g_qh;
        int b = m0 >> 12;
        int hw0 = m0 & 4095;
        #pragma unroll
        for (int mt = 0; mt < 2; mt++)
            #pragma unroll
            for (int nt = 0; nt < 8; nt++) {
                int row = (warpM << 5) + (mt << 4) + g;
                int col = d0 + (warpN << 6) + (nt << 3) + (tig << 1);
                float* c = acc[mt][nt];
                size_t bi = (size_t)((b << 8) + col) * 4096 + hw0;
                dst[bi + row]            = __float2half(c[0]);
                dst[bi + 4096 + row]     = __float2half(c[1]);
                dst[bi + row + 8]        = __float2half(c[2]);
                dst[bi + 4096 + row + 8] = __float2half(c[3]);
            }
    } else {
        __half* dst = (which == 2) ? g_vch : g_vsh;
        #pragma unroll
        for (int mt = 0; mt < 2; mt++)
            #pragma unroll
            for (int nt = 0; nt < 8; nt++) {
                int row = (warpM << 5) + (mt << 4) + g;
                int col = d0 + (warpN << 6) + (nt << 3) + (tig << 1);
                float* c = acc[mt][nt];
                *(__half2*)&dst[(size_t)(m0 + row) * 256 + col] =
                    __floats2half2_rn(c[0], c[1]);
                *(__half2*)&dst[(size_t)(m0 + row + 8) * 256 + col] =
                    __floats2half2_rn(c[2], c[3]);
            }
    }
}

// ---------------------------------------------------------------------------
// K2: per-(b,c) attention logits (fp16 mma via ldmatrix).
// Single natural smem image [h][w]; phase 1 uses plain ldmatrix,
// phase 2 (Q^T K) uses ldmatrix.trans on the SAME image.
// ---------------------------------------------------------------------------
__global__ __launch_bounds__(256) void k_attn(void)
{
    __shared__ alignas(16) __half Qs[64][72];
    __shared__ alignas(16) __half Ks[64][72];
    int bc = blockIdx.x;
    const __half* Q = g_qh + (size_t)bc * 4096;
    const __half* K = g_kh + (size_t)bc * 4096;
    int tid = threadIdx.x, lane = tid & 31, wid = tid >> 5;
    int warpM = wid >> 1, warpN = wid & 1;
    int g = lane >> 2, tig = lane & 3;
    int sub = lane >> 3, r = lane & 7;
    int rowA = warpM << 4;          // 16-row A tile base
    int colB = warpN << 5;          // 32-col B tile base

    #pragma unroll
    for (int l = 0; l < 2; l++) {
        int idx = tid + (l << 8);          // 0..511 rows-of-8
        int h = idx >> 3, wq = (idx & 7) << 3;
        *(uint4*)&Qs[h][wq] = *(const uint4*)&Q[(h << 6) + wq];
        *(uint4*)&Ks[h][wq] = *(const uint4*)&K[(h << 6) + wq];
    }
    __syncthreads();

    {   // Phase 1: S1[h][gg] = sum_w Q[h][w] K[gg][w]
        float acc[4][4] = {};
        #pragma unroll
        for (int ks = 0; ks < 4; ks++) {
            int kh = ks << 4;
            unsigned a[4], bf[4][2];
            ldsm_x4(a[0], a[1], a[2], a[3],
                sptr(&Qs[rowA + ((sub & 1) << 3) + r][kh + ((sub >> 1) << 3)]));
            #pragma unroll
            for (int np = 0; np < 2; np++) {
                unsigned b0, b1, b2, b3;
                ldsm_x4(b0, b1, b2, b3,
                    sptr(&Ks[colB + (np << 4) + ((sub >> 1) << 3) + r][kh + ((sub & 1) << 3)]));
                bf[2 * np][0] = b0; bf[2 * np][1] = b1;
                bf[2 * np + 1][0] = b2; bf[2 * np + 1][1] = b3;
            }
            #pragma unroll
            for (int nt = 0; nt < 4; nt++) mma_f16(acc[nt], a, bf[nt]);
        }
        float* out = g_as + (size_t)bc * 4096;
        #pragma unroll
        for (int nt = 0; nt < 4; nt++) {
            int row = rowA + g;
            int col = colB + (nt << 3) + (tig << 1);
            *(float2*)&out[row * 64 + col]       = make_float2(acc[nt][0], acc[nt][1]);
            *(float2*)&out[(row + 8) * 64 + col] = make_float2(acc[nt][2], acc[nt][3]);
        }
    }
    {   // Phase 2: S2[w][v] = sum_h Q[h][w] K[h][v]  (trans reads of same image)
        float acc[4][4] = {};
        #pragma unroll
        for (int ks = 0; ks < 4; ks++) {
            int kh = ks << 4;
            unsigned a[4], bf[4][2];
            ldsm_x4t(a[0], a[1], a[2], a[3],
                sptr(&Qs[kh + ((sub >> 1) << 3) + r][rowA + ((sub & 1) << 3)]));
            #pragma unroll
            for (int np = 0; np < 2; np++) {
                unsigned b0, b1, b2, b3;
                ldsm_x4t(b0, b1, b2, b3,
                    sptr(&Ks[kh + ((sub & 1) << 3) + r][colB + (np << 4) + ((sub >> 1) << 3)]));
                bf[2 * np][0] = b0; bf[2 * np][1] = b1;
                bf[2 * np + 1][0] = b2; bf[2 * np + 1][1] = b3;
            }
            #pragma unroll
            for (int nt = 0; nt < 4; nt++) mma_f16(acc[nt], a, bf[nt]);
        }
        float* out = g_ac + (size_t)bc * 4096;
        #pragma unroll
        for (int nt = 0; nt < 4; nt++) {
            int row = rowA + g;
            int col = colB + (nt << 3) + (tig << 1);
            *(float2*)&out[row * 64 + col]       = make_float2(acc[nt][0], acc[nt][1]);
            *(float2*)&out[(row + 8) * 64 + col] = make_float2(acc[nt][2], acc[nt][3]);
        }
    }
}

// ---------------------------------------------------------------------------
// K3: transpose-softmax over channel axis; which=1 also emits pool partials.
// ---------------------------------------------------------------------------
__global__ __launch_bounds__(256) void k_softmax_t(void)
{
    __shared__ float tile[256][33];
    __shared__ float red[8][32];
    __shared__ float Mv[32], Iv[32];
    int which = blockIdx.y;
    const float* src = which ? g_ac : g_as;
    __half* dst = which ? g_ach : g_ash;
    int blk = blockIdx.x;
    int b = blk >> 7;
    int pos0 = (blk & 127) << 5;
    int tid = threadIdx.x, lane = tid & 31, wid = tid >> 5;

    const float* sb = src + (size_t)(b << 8) * 4096 + pos0;
    #pragma unroll 8
    for (int it = 0; it < 32; it++) {
        int c = (it << 3) + wid;
        tile[c][lane] = sb[(size_t)c * 4096 + lane];
    }
    __syncthreads();

    int pos = lane, cq = wid;
    int c0 = cq << 5;
    float m = -3.0e38f;
    #pragma unroll
    for (int j = 0; j < 32; j++) m = fmaxf(m, tile[c0 + j][pos]);
    red[cq][pos] = m;
    __syncthreads();
    if (tid < 32) {
        float M = -3.0e38f;
        #pragma unroll
        for (int j = 0; j < 8; j++) M = fmaxf(M, red[j][tid]);
        Mv[tid] = M;
    }
    __syncthreads();
    float M = Mv[pos];
    float s = 0.f;
    #pragma unroll
    for (int j = 0; j < 32; j++) {
        float e = __expf(tile[c0 + j][pos] - M);
        tile[c0 + j][pos] = e;
        s += e;
    }
    red[cq][pos] = s;
    __syncthreads();
    if (tid < 32) {
        float S = 0.f;
        #pragma unroll
        for (int j = 0; j < 8; j++) S += red[j][tid];
        Iv[tid] = 1.0f / S;
    }
    __syncthreads();
    float inv = Iv[pos];

    size_t rowo = ((size_t)((b << 12) + pos0 + pos)) << 8;
    #pragma unroll
    for (int q = 0; q < 4; q++) {
        int cb = c0 + (q << 3);
        uint4 u;
        u.x = packh2(tile[cb + 0][pos] * inv, tile[cb + 1][pos] * inv);
        u.y = packh2(tile[cb + 2][pos] * inv, tile[cb + 3][pos] * inv);
        u.z = packh2(tile[cb + 4][pos] * inv, tile[cb + 5][pos] * inv);
        u.w = packh2(tile[cb + 6][pos] * inv, tile[cb + 7][pos] * inv);
        *(uint4*)&dst[rowo + cb] = u;
    }

    if (which) {
        int c = tid;
        float sp = 0.f;
        #pragma unroll 8
        for (int j = 0; j < 32; j++) sp += tile[c][j] * Iv[j];
        g_poolp[(size_t)((b << 7) + (blk & 127)) * 256 + c] = sp;
    }
}

// ---------------------------------------------------------------------------
// K4: conv3x3 s2 p1 + relu, channels-last. BM=128, BN=128, K=2304.
// ---------------------------------------------------------------------------
__global__ __launch_bounds__(256) void k_conv(void)
{
    __shared__ unsigned As[128][20];
    __shared__ unsigned Bs[128][20];
    int m0 = blockIdx.x << 7;
    int n0 = blockIdx.y << 7;
    int tid = threadIdx.x, lane = tid & 31, wid = tid >> 5;
    int warpM = wid >> 1, warpN = wid & 1;
    int g = lane >> 2, tig = lane & 3;
    int b = m0 >> 10;
    float acc[2][8][4] = {};
    uint4 ra[2], rb[2];

    auto gload = [&](int k0) {
        int tap = k0 >> 8;
        int ky = tap / 3, kx = tap - ky * 3;
        int cib = (k0 & 255) + ((tid & 3) << 3);
        #pragma unroll
        for (int l = 0; l < 2; l++) {
            int idx = tid + (l << 8);
            int mrow = idx >> 2;
            int r = (m0 + mrow) & 1023;
            int oy = r >> 5, ox = r & 31;
            int iy = 2 * oy - 1 + ky, ix = 2 * ox - 1 + kx;
            if ((unsigned)iy < 64u && (unsigned)ix < 64u)
                ra[l] = *(const uint4*)&g_ash[(((size_t)(b << 12) + (iy << 6) + ix) << 8) + cib];
            else
                ra[l] = make_uint4(0u, 0u, 0u, 0u);
            rb[l] = *(const uint4*)&g_wch[(size_t)(n0 + mrow) * 2304 + k0 + ((idx & 3) << 3)];
        }
    };
    auto sstore = [&]() {
        #pragma unroll
        for (int l = 0; l < 2; l++) {
            int idx = tid + (l << 8);
            *(uint4*)&As[idx >> 2][(idx & 3) << 2] = ra[l];
            *(uint4*)&Bs[idx >> 2][(idx & 3) << 2] = rb[l];
        }
    };

    gload(0); sstore(); __syncthreads();
    for (int k0 = 0; k0 < 2304; k0 += 32) {
        bool more = (k0 + 32) < 2304;
        if (more) gload(k0 + 32);
        #pragma unroll
        for (int ks = 0; ks < 2; ks++) {
            int kb = ks << 3;
            unsigned a[2][4], bf[8][2];
            #pragma unroll
            for (int mt = 0; mt < 2; mt++) {
                int row = (warpM << 5) + (mt << 4) + g;
                a[mt][0] = As[row][kb + tig];     a[mt][1] = As[row + 8][kb + tig];
                a[mt][2] = As[row][kb + 4 + tig]; a[mt][3] = As[row + 8][kb + 4 + tig];
            }
            #pragma unroll
            for (int nt = 0; nt < 8; nt++) {
                int col = (warpN << 6) + (nt << 3) + g;
                bf[nt][0] = Bs[col][kb + tig]; bf[nt][1] = Bs[col][kb + 4 + tig];
            }
            #pragma unroll
            for (int mt = 0; mt < 2; mt++)
                #pragma unroll
                for (int nt = 0; nt < 8; nt++)
                    mma_f16(acc[mt][nt], a[mt], bf[nt]);
        }
        __syncthreads();
        if (more) { sstore(); __syncthreads(); }
    }

    #pragma unroll
    for (int mt = 0; mt < 2; mt++)
        #pragma unroll
        for (int nt = 0; nt < 8; nt++) {
            int row = (warpM << 5) + (mt << 4) + g;
            int col = n0 + (warpN << 6) + (nt << 3) + (tig << 1);
            float* c = acc[mt][nt];
            int r1 = (m0 + row) & 1023;
            *(__half2*)&g_c1h[(((size_t)(b << 10) + r1) << 8) + col] =
                __floats2half2_rn(fmaxf(c[0], 0.f), fmaxf(c[1], 0.f));
            int r2 = (m0 + row + 8) & 1023;
            *(__half2*)&g_c1h[(((size_t)(b << 10) + r2) << 8) + col] =
                __floats2half2_rn(fmaxf(c[2], 0.f), fmaxf(c[3], 0.f));
        }
}

// ---------------------------------------------------------------------------
// K6: convT 4x4 s2 p1 + relu by parity class, channels-last.
// ---------------------------------------------------------------------------
__global__ __launch_bounds__(256) void k_convt(void)
{
    __shared__ unsigned As[128][20];
    __shared__ unsigned Bs[128][20];
    int cl = blockIdx.z;
    int py = cl >> 1, px = cl & 1;
    int m0 = blockIdx.x << 7;
    int n0 = blockIdx.y << 7;
    int tid = threadIdx.x, lane = tid & 31, wid = tid >> 5;
    int warpM = wid >> 1, warpN = wid & 1;
    int g = lane >> 2, tig = lane & 3;
    int b = m0 >> 10;
    float acc[2][8][4] = {};
    uint4 ra[2], rb[2];

    auto gload = [&](int k0) {
        int t = k0 >> 8;
        int tyk = t >> 1, txk = t & 1;
        int cib = (k0 & 255) + ((tid & 3) << 3);
        #pragma unroll
        for (int l = 0; l < 2; l++) {
            int idx = tid + (l << 8);
            int mrow = idx >> 2;
            int r = (m0 + mrow) & 1023;
            int ys = r >> 5, xs = r & 31;
            int ii = ys + py - tyk, jj = xs + px - txk;
            if ((unsigned)ii < 32u && (unsigned)jj < 32u)
                ra[l] = *(const uint4*)&g_c1h[(((size_t)(b << 10) + (ii << 5) + jj) << 8) + cib];
            else
                ra[l] = make_uint4(0u, 0u, 0u, 0u);
            rb[l] = *(const uint4*)&g_wt2[(((size_t)((cl << 8) + n0 + mrow)) << 10) + k0 + ((idx & 3) << 3)];
        }
    };
    auto sstore = [&]() {
        #pragma unroll
        for (int l = 0; l < 2; l++) {
            int idx = tid + (l << 8);
            *(uint4*)&As[idx >> 2][(idx & 3) << 2] = ra[l];
            *(uint4*)&Bs[idx >> 2][(idx & 3) << 2] = rb[l];
        }
    };

    gload(0); sstore(); __syncthreads();
    for (int k0 = 0; k0 < 1024; k0 += 32) {
        bool more = (k0 + 32) < 1024;
        if (more) gload(k0 + 32);
        #pragma unroll
        for (int ks = 0; ks < 2; ks++) {
            int kb = ks << 3;
            unsigned a[2][4], bf[8][2];
            #pragma unroll
            for (int mt = 0; mt < 2; mt++) {
                int row = (warpM << 5) + (mt << 4) + g;
                a[mt][0] = As[row][kb + tig];     a[mt][1] = As[row + 8][kb + tig];
                a[mt][2] = As[row][kb + 4 + tig]; a[mt][3] = As[row + 8][kb + 4 + tig];
            }
            #pragma unroll
            for (int nt = 0; nt < 8; nt++) {
                int col = (warpN << 6) + (nt << 3) + g;
                bf[nt][0] = Bs[col][kb + tig]; bf[nt][1] = Bs[col][kb + 4 + tig];
            }
            #pragma unroll
            for (int mt = 0; mt < 2; mt++)
                #pragma unroll
                for (int nt = 0; nt < 8; nt++)
                    mma_f16(acc[mt][nt], a[mt], bf[nt]);
        }
        __syncthreads();
        if (more) { sstore(); __syncthreads(); }
    }

    #pragma unroll
    for (int mt = 0; mt < 2; mt++)
        #pragma unroll
        for (int nt = 0; nt < 8; nt++) {
            int row = (warpM << 5) + (mt << 4) + g;
            int col = n0 + (warpN << 6) + (nt << 3) + (tig << 1);
            float* c = acc[mt][nt];
            int mm1 = m0 + row;
            int ys1 = (mm1 >> 5) & 31, xs1 = mm1 & 31;
            size_t o1 = (((size_t)(b << 12) + (((ys1 << 1) + py) << 6) + (xs1 << 1) + px) << 8) + col;
            *(__half2*)&g_sbh[o1] = __floats2half2_rn(fmaxf(c[0], 0.f), fmaxf(c[1], 0.f));
            int mm2 = mm1 + 8;
            int ys2 = (mm2 >> 5) & 31, xs2 = mm2 & 31;
            size_t o2 = (((size_t)(b << 12) + (((ys2 << 1) + py) << 6) + (xs2 << 1) + px) << 8) + col;
            *(__half2*)&g_sbh[o2] = __floats2half2_rn(fmaxf(c[2], 0.f), fmaxf(c[3], 0.f));
        }
}

// ---------------------------------------------------------------------------
// K8: SE MLP (combines 128 pool partials per b)
// ---------------------------------------------------------------------------
__global__ __launch_bounds__(256) void k_se(const float* __restrict__ Wc1,
                                            const float* __restrict__ Wc2)
{
    int b = blockIdx.x;
    __shared__ float pool[256];
    __shared__ float hid[64];
    int t = threadIdx.x;
    float s = 0.f;
    #pragma unroll 16
    for (int j = 0; j < 128; j++) s += g_poolp[(size_t)((b << 7) + j) * 256 + t];
    pool[t] = s * (1.0f / 4096.0f);
    __syncthreads();
    if (t < 64) {
        float h = 0.f;
        for (int c = 0; c < 256; c++) h += pool[c] * Wc1[t * 256 + c];
        hid[t] = fmaxf(h, 0.f);
    }
    __syncthreads();
    float v = 0.f;
    #pragma unroll
    for (int j = 0; j < 64; j++) v += hid[j] * Wc2[t * 64 + j];
    g_gate[(b << 8) + t] = 1.0f / (1.0f + __expf(-v));
}

// ---------------------------------------------------------------------------
// K9: fused residual + LayerNorm. All inputs channels-last; warp per position.
// ---------------------------------------------------------------------------
__global__ __launch_bounds__(256) void k_fuse(const float* __restrict__ x,
                                              const float* __restrict__ gamma,
                                              const float* __restrict__ beta,
                                              float* __restrict__ out)
{
    int wid = threadIdx.x >> 5, lane = threadIdx.x & 31;
    int pos = (blockIdx.x << 3) + wid;
    int b = pos >> 12;
    size_t row = (size_t)pos << 8;
    int c0 = lane << 3;

    float4 x0 = *(const float4*)&x[row + c0];
    float4 x1 = *(const float4*)&x[row + c0 + 4];
    float vs[8], vc[8], sb[8], ac[8];
    unp8(*(const uint4*)&g_vsh[row + c0], vs);
    unp8(*(const uint4*)&g_vch[row + c0], vc);
    unp8(*(const uint4*)&g_sbh[row + c0], sb);
    unp8(*(const uint4*)&g_ach[row + c0], ac);
    float4 g0 = *(const float4*)&g_gate[(b << 8) + c0];
    float4 g1 = *(const float4*)&g_gate[(b << 8) + c0 + 4];
    float xs[8] = {x0.x, x0.y, x0.z, x0.w, x1.x, x1.y, x1.z, x1.w};
    float gt[8] = {g0.x, g0.y, g0.z, g0.w, g1.x, g1.y, g1.z, g1.w};

    float y[8];
    float s1 = 0.f, s2 = 0.f;
    #pragma unroll
    for (int j = 0; j < 8; j++) {
        y[j] = xs[j] + sb[j] * vs[j] + gt[j] * ac[j] * vc[j];
        s1 += y[j]; s2 += y[j] * y[j];
    }
    #pragma unroll
    for (int o = 16; o > 0; o >>= 1) {
        s1 += __shfl_xor_sync(0xffffffffu, s1, o);
        s2 += __shfl_xor_sync(0xffffffffu, s2, o);
    }
    float mu = s1 * (1.0f / 256.0f);
    float var = s2 * (1.0f / 256.0f) - mu * mu;
    float ri = rsqrtf(var + 1e-5f);

    float4 gm0 = *(const float4*)&gamma[c0];
    float4 gm1 = *(const float4*)&gamma[c0 + 4];
    float4 bt0 = *(const float4*)&beta[c0];
    float4 bt1 = *(const float4*)&beta[c0 + 4];
    float gm[8] = {gm0.x, gm0.y, gm0.z, gm0.w, gm1.x, gm1.y, gm1.z, gm1.w};
    float bt[8] = {bt0.x, bt0.y, bt0.z, bt0.w, bt1.x, bt1.y, bt1.z, bt1.w};
    float4 o0, o1;
    o0.x = (y[0] - mu) * ri * gm[0] + bt[0];
    o0.y = (y[1] - mu) * ri * gm[1] + bt[1];
    o0.z = (y[2] - mu) * ri * gm[2] + bt[2];
    o0.w = (y[3] - mu) * ri * gm[3] + bt[3];
    o1.x = (y[4] - mu) * ri * gm[4] + bt[4];
    o1.y = (y[5] - mu) * ri * gm[5] + bt[5];
    o1.z = (y[6] - mu) * ri * gm[6] + bt[6];
    o1.w = (y[7] - mu) * ri * gm[7] + bt[7];
    *(float4*)&out[row + c0]     = o0;
    *(float4*)&out[row + c0 + 4] = o1;
}

// ---------------------------------------------------------------------------
extern "C" void kernel_launch(void* const* d_in, const int* in_sizes, int n_in,
                              void* d_out, int out_size)
{
    const float* x      = (const float*)d_in[0];
    const float* Wq     = (const float*)d_in[1];
    const float* Wk     = (const float*)d_in[2];
    const float* Wvc    = (const float*)d_in[3];
    const float* Wvs    = (const float*)d_in[4];
    const float* Wc1    = (const float*)d_in[5];
    const float* Wc2    = (const float*)d_in[6];
    const float* Wconv  = (const float*)d_in[7];
    const float* Wconvt = (const float*)d_in[8];
    const float* gamma  = (const float*)d_in[9];
    const float* beta   = (const float*)d_in[10];
    float* out = (float*)d_out;

    k_packc<<<256, 256>>>(Wconv);
    k_packt<<<1024, 256>>>(Wconvt);
    k_proj <<<dim3(512, 8), 256>>>(x, Wq, Wk, Wvc, Wvs);
    k_attn <<<4096, 256>>>();
    k_softmax_t<<<dim3(2048, 2), 256>>>();
    k_conv <<<dim3(128, 2), 256>>>();
    k_convt<<<dim3(128, 2, 4), 256>>>();
    k_se   <<<16, 256>>>(Wc1, Wc2);
    k_fuse <<<8192, 256>>>(x, gamma, beta, out);
}